// round 8
// baseline (speedup 1.0000x reference)
#include <cuda_runtime.h>
#include <cstdint>

#define Bsz 2048
#define Tsz 512
#define Asz 32
#define Hsz 16
#define NCHUNK (Tsz / 8)

typedef unsigned long long u64;
typedef unsigned int u32;

__device__ __forceinline__ void unpack2(u64 v, float& lo, float& hi) {
    asm("mov.b64 {%0, %1}, %2;" : "=f"(lo), "=f"(hi) : "l"(v));
}
__device__ __forceinline__ u64 fma2(u64 a, u64 b, u64 c) {
    u64 d; asm("fma.rn.f32x2 %0, %1, %2, %3;" : "=l"(d) : "l"(a), "l"(b), "l"(c)); return d;
}
__device__ __forceinline__ u64 add2(u64 a, u64 b) {
    u64 d; asm("add.rn.f32x2 %0, %1, %2;" : "=l"(d) : "l"(a), "l"(b)); return d;
}
__device__ __forceinline__ float hsum2(u64 v) {
    float lo, hi; unpack2(v, lo, hi); return lo + hi;
}
__device__ __forceinline__ float sigmoidf_(float x) {
    return __fdividef(1.0f, 1.0f + __expf(-x));
}
__device__ __forceinline__ u32 smaddr(const void* p) {
    return (u32)__cvta_generic_to_shared(p);
}
__device__ __forceinline__ void cp16(u32 s, const void* g) {
    asm volatile("cp.async.ca.shared.global [%0], [%1], 16;" :: "r"(s), "l"(g));
}
#define CP_COMMIT() asm volatile("cp.async.commit_group;" ::: "memory")
#define CP_WAIT1()  asm volatile("cp.async.wait_group 1;" ::: "memory")

// ============================================================================
// Fused LSTM: CTA = 128 threads = 4 warps = 4 batch elements.
//   2 consumer warps (half-warp per element): recurrence only, lane j owns
//     h-index j, all 4 gates in-lane (no shfl on the c chain).
//   2 producer warps: pregates (x W_ih^T + b) one chunk ahead via cp.async
//     double buffer, PLUS actor/critic heads one chunk behind (h from a
//     16-deep smem ring). Heads never touch the consumer's critical path.
// Roles swap with blockIdx parity so SMSPs see a balanced instruction mix.
// One __syncthreads per chunk. pg never touches HBM.
// ============================================================================
__global__ void __launch_bounds__(128, 4) lstm_fused(
    const float* __restrict__ xin, const float* __restrict__ masks,
    const float* __restrict__ h0, const float* __restrict__ c0,
    const float* __restrict__ w_ih, const float* __restrict__ w_hh,
    const float* __restrict__ b_ih, const float* __restrict__ b_hh,
    const float* __restrict__ w_actor, const float* __restrict__ b_actor,
    const float* __restrict__ w_critic, const float* __restrict__ b_critic,
    float* __restrict__ actor, float* __restrict__ critic,
    float* __restrict__ hT, float* __restrict__ cT)
{
    __shared__ __align__(16) float pgsm[4][2][8 * 64];  // 16KB
    __shared__ __align__(16) float xsm[4][2][8 * 32];   // 8KB
    __shared__ __align__(16) float hbuf[4][16][16];     // 4KB ring: slot t&15 = h_t

    const int tid  = threadIdx.x;
    const int w    = tid >> 5;
    const int lane = tid & 31;
    const int pair = w >> 1;            // 0: warps {0,1}, 1: warps {2,3}
    const int sub  = w & 1;             // which element pair within the role
    const bool is_prod = ((pair ^ (blockIdx.x & 1)) != 0);
    const int b0   = blockIdx.x * 4;

    if (is_prod) {
        // ---------------- PRODUCER (elements e0 = 2*sub, e0+1) --------------
        const int e0 = 2 * sub;
        u64 wA[16], wB[16];
        {
            const u64* pA = (const u64*)(w_ih + lane * 32);
            const u64* pB = (const u64*)(w_ih + (32 + lane) * 32);
#pragma unroll
            for (int k = 0; k < 16; k++) { wA[k] = pA[k]; wB[k] = pB[k]; }
        }
        const float bsA = b_ih[lane] + b_hh[lane];
        const float bsB = b_ih[32 + lane] + b_hh[32 + lane];
        u64 wa[8], wc[8];                 // actor row = lane; critic weights
        {
            const u64* pa = (const u64*)(w_actor + lane * 16);
            const u64* pc = (const u64*)w_critic;
#pragma unroll
            for (int k = 0; k < 8; k++) { wa[k] = pa[k]; wc[k] = pc[k]; }
        }
        const float bact = b_actor[lane];
        const float bcr  = b_critic[0];

        const float* xb0 = xin + (size_t)(b0 + e0) * Tsz * Asz;
        const float* xb1 = xin + (size_t)(b0 + e0 + 1) * Tsz * Asz;
        float* act0 = actor + (size_t)(b0 + e0) * Tsz * Asz;
        float* act1 = actor + (size_t)(b0 + e0 + 1) * Tsz * Asz;
        float* cr0  = critic + (size_t)(b0 + e0) * Tsz;
        float* cr1  = critic + (size_t)(b0 + e0 + 1) * Tsz;

        auto loadx = [&](int ch) {
            const int bf = ch & 1;
            u32 d0 = smaddr(&xsm[e0][bf][0]);
            u32 d1 = smaddr(&xsm[e0 + 1][bf][0]);
            const float* s0 = xb0 + ch * 256;
            const float* s1 = xb1 + ch * 256;
            cp16(d0 + lane * 16,       s0 + lane * 4);
            cp16(d0 + lane * 16 + 512, s0 + lane * 4 + 128);
            cp16(d1 + lane * 16,       s1 + lane * 4);
            cp16(d1 + lane * 16 + 512, s1 + lane * 4 + 128);
        };
        auto comp = [&](int ch) {
            const int bf = ch & 1;
#pragma unroll
            for (int ee = 0; ee < 2; ee++) {
#pragma unroll
                for (int s = 0; s < 8; s++) {
                    const ulonglong2* xp = (const ulonglong2*)&xsm[e0 + ee][bf][s * 32];
                    u64 a0 = 0, a1 = 0, g0 = 0, g1 = 0;
#pragma unroll
                    for (int q = 0; q < 8; q++) {
                        const ulonglong2 v = xp[q];
                        a0 = fma2(wA[2 * q],     v.x, a0);
                        a1 = fma2(wA[2 * q + 1], v.y, a1);
                        g0 = fma2(wB[2 * q],     v.x, g0);
                        g1 = fma2(wB[2 * q + 1], v.y, g1);
                    }
                    float2 o;
                    o.x = hsum2(add2(a0, a1)) + bsA;
                    o.y = hsum2(add2(g0, g1)) + bsB;
                    *(float2*)&pgsm[e0 + ee][bf][s * 64 + 2 * lane] = o;
                }
            }
        };
        auto heads = [&](int cc) {       // heads for chunk cc (h already final)
            const int t0 = cc * 8;
#pragma unroll
            for (int ee = 0; ee < 2; ee++) {
                float* ab = ee ? act1 : act0;
#pragma unroll
                for (int s = 0; s < 8; s++) {
                    const int t = t0 + s;
                    const ulonglong2* hp = (const ulonglong2*)&hbuf[e0 + ee][t & 15][0];
                    u64 a0 = 0, a1 = 0;
#pragma unroll
                    for (int q = 0; q < 4; q++) {
                        const ulonglong2 v = hp[q];
                        a0 = fma2(wa[2 * q],     v.x, a0);
                        a1 = fma2(wa[2 * q + 1], v.y, a1);
                    }
                    ab[t * Asz + lane] = hsum2(add2(a0, a1)) + bact;
                }
            }
            if (lane < 16) {             // critic: lane -> (elem, step)
                const int ee = lane >> 3, s = lane & 7;
                const int t = t0 + s;
                const u64* hp = (const u64*)&hbuf[e0 + ee][t & 15][0];
                u64 a0 = 0, a1 = 0;
#pragma unroll
                for (int k = 0; k < 4; k++) {
                    a0 = fma2(wc[2 * k],     hp[2 * k],     a0);
                    a1 = fma2(wc[2 * k + 1], hp[2 * k + 1], a1);
                }
                (ee ? cr1 : cr0)[t] = hsum2(add2(a0, a1)) + bcr;
            }
        };

        loadx(0); CP_COMMIT();
        loadx(1); CP_COMMIT();
        CP_WAIT1();
        comp(0);
        __syncthreads();                 // pg chunk 0 ready

        for (int cc = 0; cc < NCHUNK; cc++) {
            if (cc + 2 < NCHUNK) loadx(cc + 2);
            CP_COMMIT();
            CP_WAIT1();
            if (cc + 1 < NCHUNK) comp(cc + 1);
            if (cc >= 1) heads(cc - 1);  // consumer finished chunk cc-1 at last sync
            __syncthreads();
        }
        heads(NCHUNK - 1);               // after final sync; smem still live
    } else {
        // ---------------- CONSUMER (half-warp per element) ------------------
        const int e = 2 * sub + (lane >> 4);
        const int j = lane & 15;
        const int b = b0 + e;

        u64 whI[8], whF[8], whG[8], whO[8];
        {
            const u64* pI = (const u64*)(w_hh + j * 16);
            const u64* pF = (const u64*)(w_hh + (16 + j) * 16);
            const u64* pG = (const u64*)(w_hh + (32 + j) * 16);
            const u64* pO = (const u64*)(w_hh + (48 + j) * 16);
#pragma unroll
            for (int k = 0; k < 8; k++) {
                whI[k] = pI[k]; whF[k] = pF[k]; whG[k] = pG[k]; whO[k] = pO[k];
            }
        }
        const float* mb = masks + (size_t)b * Tsz;
        float c = c0[b * Hsz + j];
        hbuf[e][15][j] = h0[b * Hsz + j];       // h_{-1} at slot 15
        float m_cur = mb[0];
        float h2 = 0.0f;

        __syncthreads();                         // match producer prologue

        for (int cc = 0; cc < NCHUNK; cc++) {
#pragma unroll
            for (int s = 0; s < 8; s++) {
                const int t = cc * 8 + s;
                const float m = m_cur;
                m_cur = mb[(t + 1 < Tsz) ? t + 1 : Tsz - 1];

                u64 hv[8];                        // h_{t-1} broadcast
                {
                    const ulonglong2* hp = (const ulonglong2*)&hbuf[e][(t + 15) & 15][0];
#pragma unroll
                    for (int q = 0; q < 4; q++) {
                        const ulonglong2 v = hp[q];
                        hv[2 * q] = v.x; hv[2 * q + 1] = v.y;
                    }
                }
                u64 aI = 0, aF = 0, aG = 0, aO = 0;
#pragma unroll
                for (int k = 0; k < 8; k++) {
                    aI = fma2(whI[k], hv[k], aI);
                    aF = fma2(whF[k], hv[k], aF);
                    aG = fma2(whG[k], hv[k], aG);
                    aO = fma2(whO[k], hv[k], aO);
                }
                const float sI = hsum2(aI), sF = hsum2(aF);
                const float sG = hsum2(aG), sO = hsum2(aO);

                const float2 pIG = *(const float2*)&pgsm[e][cc & 1][s * 64 + 2 * j];
                const float2 pFO = *(const float2*)&pgsm[e][cc & 1][s * 64 + 32 + 2 * j];

                const float gI = fmaf(m, sI, pIG.x);
                const float gG = fmaf(m, sG, pIG.y);
                const float gF = fmaf(m, sF, pFO.x);
                const float gO = fmaf(m, sO, pFO.y);

                const float vI = sigmoidf_(gI);
                const float vF = sigmoidf_(gF);
                const float vO = sigmoidf_(gO);
                const float vG = fmaf(2.0f, sigmoidf_(2.0f * gG), -1.0f); // tanh

                c  = fmaf(vF, c * m, vI * vG);
                h2 = vO * fmaf(2.0f, sigmoidf_(2.0f * c), -1.0f);

                hbuf[e][t & 15][j] = h2;
                __syncwarp();
            }
            __syncthreads();
        }

        hT[b * Hsz + j] = h2;
        cT[b * Hsz + j] = c;
    }
}

extern "C" void kernel_launch(void* const* d_in, const int* in_sizes, int n_in,
                              void* d_out, int out_size) {
    const float* xin      = (const float*)d_in[0];
    const float* masks    = (const float*)d_in[1];
    const float* h0       = (const float*)d_in[2];
    const float* c0       = (const float*)d_in[3];
    const float* w_ih     = (const float*)d_in[4];
    const float* w_hh     = (const float*)d_in[5];
    const float* b_ih     = (const float*)d_in[6];
    const float* b_hh     = (const float*)d_in[7];
    const float* w_actor  = (const float*)d_in[8];
    const float* b_actor  = (const float*)d_in[9];
    const float* w_critic = (const float*)d_in[10];
    const float* b_critic = (const float*)d_in[11];

    float* out    = (float*)d_out;
    float* actor  = out;
    float* critic = actor + (size_t)Bsz * Tsz * Asz;
    float* hT     = critic + (size_t)Bsz * Tsz;
    float* cT     = hT + (size_t)Bsz * Hsz;

    lstm_fused<<<Bsz / 4, 128>>>(xin, masks, h0, c0, w_ih, w_hh, b_ih, b_hh,
                                 w_actor, b_actor, w_critic, b_critic,
                                 actor, critic, hT, cT);
}

// round 9
// speedup vs baseline: 1.1003x; 1.1003x over previous
#include <cuda_runtime.h>
#include <cstdint>

#define Bsz 2048
#define Tsz 512
#define Asz 32
#define Hsz 16
#define NCHUNK (Tsz / 8)

typedef unsigned long long u64;
typedef unsigned int u32;

__device__ __forceinline__ void unpack2(u64 v, float& lo, float& hi) {
    asm("mov.b64 {%0, %1}, %2;" : "=f"(lo), "=f"(hi) : "l"(v));
}
__device__ __forceinline__ u64 fma2(u64 a, u64 b, u64 c) {
    u64 d; asm("fma.rn.f32x2 %0, %1, %2, %3;" : "=l"(d) : "l"(a), "l"(b), "l"(c)); return d;
}
__device__ __forceinline__ u64 add2(u64 a, u64 b) {
    u64 d; asm("add.rn.f32x2 %0, %1, %2;" : "=l"(d) : "l"(a), "l"(b)); return d;
}
__device__ __forceinline__ float hsum2(u64 v) {
    float lo, hi; unpack2(v, lo, hi); return lo + hi;
}
__device__ __forceinline__ float sigmoidf_(float x) {
    return __fdividef(1.0f, 1.0f + __expf(-x));
}
__device__ __forceinline__ u32 smaddr(const void* p) {
    return (u32)__cvta_generic_to_shared(p);
}
__device__ __forceinline__ void cp16(u32 s, const void* g) {
    asm volatile("cp.async.ca.shared.global [%0], [%1], 16;" :: "r"(s), "l"(g));
}
#define CP_COMMIT() asm volatile("cp.async.commit_group;" ::: "memory")
#define CP_WAIT1()  asm volatile("cp.async.wait_group 1;" ::: "memory")

// ============================================================================
// CTA = 128 threads = 4 warps = 2 batch elements.
//   consumer warp (1 elem): recurrence, lo/hi gate split (lane j: i_j,g_j;
//     lane 16+j: f_j,o_j; 32 weight regs), ~45 instr/step.
//   producer warp (1 elem): pregates one chunk AHEAD (cp.async x double
//     buffer) + actor/critic heads one chunk BEHIND (h from 16-deep ring).
// Role assignment flips with blockIdx parity so SMSPs get a mixed load.
// One __syncthreads per chunk; pg never touches HBM.
// ============================================================================
__global__ void __launch_bounds__(128, 4) lstm_fused(
    const float* __restrict__ xin, const float* __restrict__ masks,
    const float* __restrict__ h0, const float* __restrict__ c0,
    const float* __restrict__ w_ih, const float* __restrict__ w_hh,
    const float* __restrict__ b_ih, const float* __restrict__ b_hh,
    const float* __restrict__ w_actor, const float* __restrict__ b_actor,
    const float* __restrict__ w_critic, const float* __restrict__ b_critic,
    float* __restrict__ actor, float* __restrict__ critic,
    float* __restrict__ hT, float* __restrict__ cT)
{
    __shared__ __align__(16) float pgsm[2][2][8 * 64];  // 8KB
    __shared__ __align__(16) float xsm[2][2][8 * 32];   // 4KB
    __shared__ __align__(16) float hbuf[2][16][16];     // 2KB ring: slot t&15 = h_t
    __shared__ __align__(16) float wc_s[16];

    const int tid  = threadIdx.x;
    const int w    = tid >> 5;
    const int lane = tid & 31;
    const int e    = w & 1;                       // element within CTA
    const bool is_prod = ((w >> 1) ^ (blockIdx.x & 1)) != 0;
    const int b    = blockIdx.x * 2 + e;

    if (tid < 16) wc_s[tid] = w_critic[tid];

    if (is_prod) {
        // ---------------- PRODUCER ----------------
        u64 wA[16], wB[16];
        {
            const u64* pA = (const u64*)(w_ih + lane * 32);
            const u64* pB = (const u64*)(w_ih + (32 + lane) * 32);
#pragma unroll
            for (int k = 0; k < 16; k++) { wA[k] = pA[k]; wB[k] = pB[k]; }
        }
        const float bsA = b_ih[lane] + b_hh[lane];
        const float bsB = b_ih[32 + lane] + b_hh[32 + lane];
        u64 wa[8];                                 // actor row = lane
        {
            const u64* pa = (const u64*)(w_actor + lane * 16);
#pragma unroll
            for (int k = 0; k < 8; k++) wa[k] = pa[k];
        }
        const float bact = b_actor[lane];
        const float bcr  = b_critic[0];

        const float* xb = xin + (size_t)b * Tsz * Asz;
        float* actb     = actor + (size_t)b * Tsz * Asz;
        float* crb      = critic + (size_t)b * Tsz;

        auto loadx = [&](int ch) {
            const int bf = ch & 1;
            u32 dst = smaddr(&xsm[e][bf][0]);
            const float* src = xb + ch * 256;
            cp16(dst + lane * 16,       src + lane * 4);
            cp16(dst + lane * 16 + 512, src + lane * 4 + 128);
        };
        auto comp = [&](int ch) {
            const int bf = ch & 1;
#pragma unroll
            for (int s = 0; s < 8; s++) {
                const ulonglong2* xp = (const ulonglong2*)&xsm[e][bf][s * 32];
                u64 a0 = 0, a1 = 0, g0 = 0, g1 = 0;
#pragma unroll
                for (int q = 0; q < 8; q++) {
                    const ulonglong2 v = xp[q];
                    a0 = fma2(wA[2 * q],     v.x, a0);
                    a1 = fma2(wA[2 * q + 1], v.y, a1);
                    g0 = fma2(wB[2 * q],     v.x, g0);
                    g1 = fma2(wB[2 * q + 1], v.y, g1);
                }
                float2 o;
                o.x = hsum2(add2(a0, a1)) + bsA;
                o.y = hsum2(add2(g0, g1)) + bsB;
                *(float2*)&pgsm[e][bf][s * 64 + 2 * lane] = o;
            }
        };
        auto heads = [&](int cc) {                 // chunk cc (h final in ring)
            const int t0 = cc * 8;
#pragma unroll
            for (int s = 0; s < 8; s++) {
                const int t = t0 + s;
                const ulonglong2* hp = (const ulonglong2*)&hbuf[e][t & 15][0];
                u64 a0 = 0, a1 = 0;
#pragma unroll
                for (int q = 0; q < 4; q++) {
                    const ulonglong2 v = hp[q];
                    a0 = fma2(wa[2 * q],     v.x, a0);
                    a1 = fma2(wa[2 * q + 1], v.y, a1);
                }
                actb[t * Asz + lane] = hsum2(add2(a0, a1)) + bact;
            }
            if (lane < 8) {                        // critic: lane = step
                const int t = t0 + lane;
                const u64* hp = (const u64*)&hbuf[e][t & 15][0];
                const u64* wc = (const u64*)wc_s;  // broadcast smem
                u64 a0 = 0, a1 = 0;
#pragma unroll
                for (int k = 0; k < 4; k++) {
                    a0 = fma2(wc[2 * k],     hp[2 * k],     a0);
                    a1 = fma2(wc[2 * k + 1], hp[2 * k + 1], a1);
                }
                crb[t] = hsum2(add2(a0, a1)) + bcr;
            }
        };

        loadx(0); CP_COMMIT();
        loadx(1); CP_COMMIT();
        CP_WAIT1();
        comp(0);
        __syncthreads();                           // pg chunk 0 ready

        for (int cc = 0; cc < NCHUNK; cc++) {
            if (cc + 2 < NCHUNK) loadx(cc + 2);
            CP_COMMIT();
            CP_WAIT1();                            // x_{cc+1} landed
            if (cc + 1 < NCHUNK) comp(cc + 1);
            if (cc >= 1) heads(cc - 1);            // h chunk cc-1 final
            __syncthreads();
        }
        heads(NCHUNK - 1);
    } else {
        // ---------------- CONSUMER (lo/hi gate split, 1 elem) --------------
        const int j = lane & 15;
        const bool hi_half = lane >= 16;

        u64 whP[8], whQ[8];                        // rows lane, 32+lane
        {
            const u64* pP = (const u64*)(w_hh + lane * 16);
            const u64* pQ = (const u64*)(w_hh + (32 + lane) * 16);
#pragma unroll
            for (int k = 0; k < 8; k++) { whP[k] = pP[k]; whQ[k] = pQ[k]; }
        }
        const float* mb = masks + (size_t)b * Tsz;
        float c = c0[b * Hsz + j];
        if (lane < 16) hbuf[e][15][lane] = h0[b * Hsz + lane];  // h_{-1}
        float m_cur = mb[0];
        float h2 = 0.0f;

        __syncthreads();                           // match producer prologue

        for (int cc = 0; cc < NCHUNK; cc++) {
#pragma unroll
            for (int s = 0; s < 8; s++) {
                const int t = cc * 8 + s;
                const float m = m_cur;
                m_cur = mb[(t + 1 < Tsz) ? t + 1 : Tsz - 1];

                u64 hv[8];                          // h_{t-1} broadcast
                {
                    const ulonglong2* hp = (const ulonglong2*)&hbuf[e][(t + 15) & 15][0];
#pragma unroll
                    for (int q = 0; q < 4; q++) {
                        const ulonglong2 v = hp[q];
                        hv[2 * q] = v.x; hv[2 * q + 1] = v.y;
                    }
                }
                u64 aP = 0, aQ = 0;
#pragma unroll
                for (int k = 0; k < 8; k++) {
                    aP = fma2(whP[k], hv[k], aP);
                    aQ = fma2(whQ[k], hv[k], aQ);
                }
                const float sP = hsum2(aP);
                const float sQ = hsum2(aQ);

                const float2 pgv = *(const float2*)&pgsm[e][cc & 1][s * 64 + 2 * lane];

                const float gP = fmaf(m, sP, pgv.x);   // lo: i, hi: f
                const float gQ = fmaf(m, sQ, pgv.y);   // lo: g, hi: o

                const float vP = sigmoidf_(gP);
                const float sgQ = sigmoidf_(hi_half ? gQ : 2.0f * gQ);
                const float vQ = hi_half ? sgQ : fmaf(2.0f, sgQ, -1.0f);  // tanh(g)

                const float p  = vP * vQ;                          // lo: i*g
                const float ig = __shfl_sync(0xffffffffu, p, j);   // hi gets i*g

                c  = fmaf(vP, c * m, ig);                          // hi: f*(c*m)+i*g
                h2 = vQ * fmaf(2.0f, sigmoidf_(2.0f * c), -1.0f);  // hi: o*tanh(c)

                if (hi_half) hbuf[e][t & 15][j] = h2;
                __syncwarp();
            }
            __syncthreads();
        }

        if (hi_half) {
            hT[b * Hsz + j] = h2;
            cT[b * Hsz + j] = c;
        }
    }
}

extern "C" void kernel_launch(void* const* d_in, const int* in_sizes, int n_in,
                              void* d_out, int out_size) {
    const float* xin      = (const float*)d_in[0];
    const float* masks    = (const float*)d_in[1];
    const float* h0       = (const float*)d_in[2];
    const float* c0       = (const float*)d_in[3];
    const float* w_ih     = (const float*)d_in[4];
    const float* w_hh     = (const float*)d_in[5];
    const float* b_ih     = (const float*)d_in[6];
    const float* b_hh     = (const float*)d_in[7];
    const float* w_actor  = (const float*)d_in[8];
    const float* b_actor  = (const float*)d_in[9];
    const float* w_critic = (const float*)d_in[10];
    const float* b_critic = (const float*)d_in[11];

    float* out    = (float*)d_out;
    float* actor  = out;
    float* critic = actor + (size_t)Bsz * Tsz * Asz;
    float* hT     = critic + (size_t)Bsz * Tsz;
    float* cT     = hT + (size_t)Bsz * Hsz;

    lstm_fused<<<Bsz / 2, 128>>>(xin, masks, h0, c0, w_ih, w_hh, b_ih, b_hh,
                                 w_actor, b_actor, w_critic, b_critic,
                                 actor, critic, hT, cT);
}